// round 8
// baseline (speedup 1.0000x reference)
#include <cuda_runtime.h>
#include <math.h>
#include <math_constants.h>

#define SEQ   128
#define BATCH 32
#define EMB   32
#define HID   16
#define VOCAB 32000
#define CIN   48           // EMB + HID

#define P1_TILES 32        // 32 blocks x 1024 vocab covers 32000 (padded)
#define CH    32           // seq chunk size
#define NCH   4            // number of chunks
#define LOG2E 1.4426950408889634f

// Scratch (no allocations allowed)
__device__ float g_H[SEQ * BATCH * HID];
__device__ float g_partS[SEQ * P1_TILES * BATCH];
__device__ float g_logZ[SEQ * BATCH];

// ---- packed f32x2 helpers (Blackwell) --------------------------------------
__device__ __forceinline__ void ffma2(unsigned long long& d,
                                      unsigned long long a,
                                      unsigned long long b) {
    asm("fma.rn.f32x2 %0, %1, %2, %0;" : "+l"(d) : "l"(a), "l"(b));
}
__device__ __forceinline__ float hsum2(unsigned long long v) {
    float lo, hi;
    asm("mov.b64 {%0, %1}, %2;" : "=f"(lo), "=f"(hi) : "l"(v));
    return lo + hi;
}
__device__ __forceinline__ unsigned long long packf2(float lo, float hi) {
    unsigned long long d;
    asm("mov.b64 %0, {%1, %2};" : "=l"(d) : "f"(lo), "f"(hi));
    return d;
}
__device__ __forceinline__ float ex2(float x) {
    float r;
    asm("ex2.approx.f32 %0, %1;" : "=f"(r) : "f"(x));
    return r;
}

// ---------------------------------------------------------------------------
// Kernel A: recurrence. 32 independent single-warp blocks (one per batch).
// ---------------------------------------------------------------------------
__global__ __launch_bounds__(32, 1)
void recur_kernel(const int*   __restrict__ idx,
                  const float* __restrict__ h0,
                  const float* __restrict__ emb,
                  const float* __restrict__ W_ih,
                  const float* __restrict__ b_ih) {
    const int b    = blockIdx.x;
    const int lane = threadIdx.x;
    const int i    = lane & 15;
    const int half = lane >> 4;

    __shared__ int   idxs[SEQ];
    __shared__ float comb[CIN];

    for (int t = lane; t < SEQ; t += 32) idxs[t] = idx[t * BATCH + b];

    float wih[24];
    const int base = half * 24;
#pragma unroll
    for (int j = 0; j < 24; j++) wih[j] = W_ih[i * CIN + base + j];
    const float bias = b_ih[i];

    __syncwarp();

    float x = emb[idxs[0] * EMB + lane];          // EMB == 32 == warp size
    float h = (lane < 16) ? h0[b * HID + lane] : 0.f;

    for (int t = 0; t < SEQ; t++) {
        comb[lane] = x;
        if (lane < 16) comb[EMB + lane] = h;
        __syncwarp();

        if (t + 1 < SEQ) x = emb[idxs[t + 1] * EMB + lane];  // prefetch

        float a0 = 0.f, a1 = 0.f, a2 = 0.f;
#pragma unroll
        for (int j = 0; j < 24; j += 3) {
            a0 += wih[j]     * comb[base + j];
            a1 += wih[j + 1] * comb[base + j + 1];
            a2 += wih[j + 2] * comb[base + j + 2];
        }
        float part = (a0 + a1) + a2;
        part += __shfl_xor_sync(0xffffffffu, part, 16);

        const float z = part + bias;
        const float e = ex2(2.f * LOG2E * z);     // e^{2z}
        const float hn = __fdividef(e - 1.f, e + 1.f);

        __syncwarp();                 // WAR before next comb writes
        if (lane < 16) {
            h = hn;
            g_H[(t * BATCH + b) * HID + i] = hn;
        }
    }
}

// ---------------------------------------------------------------------------
// Role: pass 1 (sum-exp over a 1024-vocab tile for timestep s).
// ---------------------------------------------------------------------------
__device__ __forceinline__ void p1_role(
    int s, int bx, int tid, char* sm,
    const float* __restrict__ W_ho, const float* __restrict__ b_ho) {
    const int warp = tid >> 5;
    const int lane = tid & 31;

    ulonglong2 (*hs)[4] = (ulonglong2(*)[4])sm;               // 2048 B
    float (*rS)[BATCH]  = (float(*)[BATCH])(sm + 2048);       // 1024 B

    if (tid < 128) {
        float4 hv = ((const float4*)(g_H + s * BATCH * HID))[tid];
        hv.x *= LOG2E; hv.y *= LOG2E; hv.z *= LOG2E; hv.w *= LOG2E;
        ((float4*)hs)[tid] = hv;
    }
    __syncthreads();

    const int v0 = (bx * 256 + tid) * 4;
    unsigned long long w[4][8];
    unsigned long long biasp[4];
    if (v0 < VOCAB) {
#pragma unroll
        for (int r = 0; r < 4; r++) {
            const ulonglong2* wp = (const ulonglong2*)(W_ho + (v0 + r) * HID);
            const ulonglong2 wa = wp[0], wb = wp[1], wc = wp[2], wd = wp[3];
            w[r][0] = wa.x; w[r][1] = wa.y; w[r][2] = wb.x; w[r][3] = wb.y;
            w[r][4] = wc.x; w[r][5] = wc.y; w[r][6] = wd.x; w[r][7] = wd.y;
            biasp[r] = packf2(b_ho[v0 + r] * LOG2E, 0.f);
        }
    } else {
#pragma unroll
        for (int r = 0; r < 4; r++) {
#pragma unroll
            for (int k = 0; k < 8; k++) w[r][k] = 0ull;
            biasp[r] = packf2(-126.f, 0.f);   // ex2 -> ~0
        }
    }

#pragma unroll
    for (int half = 0; half < 2; half++) {
        float v[16];
#pragma unroll
        for (int j = 0; j < 16; j++) {
            const int b = half * 16 + j;
            const ulonglong2 h01 = hs[b][0], h23 = hs[b][1];
            const ulonglong2 h45 = hs[b][2], h67 = hs[b][3];
            unsigned long long a0 = biasp[0], a1 = biasp[1];
            unsigned long long a2 = biasp[2], a3 = biasp[3];
            ffma2(a0, w[0][0], h01.x); ffma2(a0, w[0][1], h01.y);
            ffma2(a0, w[0][2], h23.x); ffma2(a0, w[0][3], h23.y);
            ffma2(a0, w[0][4], h45.x); ffma2(a0, w[0][5], h45.y);
            ffma2(a0, w[0][6], h67.x); ffma2(a0, w[0][7], h67.y);
            ffma2(a1, w[1][0], h01.x); ffma2(a1, w[1][1], h01.y);
            ffma2(a1, w[1][2], h23.x); ffma2(a1, w[1][3], h23.y);
            ffma2(a1, w[1][4], h45.x); ffma2(a1, w[1][5], h45.y);
            ffma2(a1, w[1][6], h67.x); ffma2(a1, w[1][7], h67.y);
            ffma2(a2, w[2][0], h01.x); ffma2(a2, w[2][1], h01.y);
            ffma2(a2, w[2][2], h23.x); ffma2(a2, w[2][3], h23.y);
            ffma2(a2, w[2][4], h45.x); ffma2(a2, w[2][5], h45.y);
            ffma2(a2, w[2][6], h67.x); ffma2(a2, w[2][7], h67.y);
            ffma2(a3, w[3][0], h01.x); ffma2(a3, w[3][1], h01.y);
            ffma2(a3, w[3][2], h23.x); ffma2(a3, w[3][3], h23.y);
            ffma2(a3, w[3][4], h45.x); ffma2(a3, w[3][5], h45.y);
            ffma2(a3, w[3][6], h67.x); ffma2(a3, w[3][7], h67.y);
            v[j] = (ex2(hsum2(a0)) + ex2(hsum2(a1)))
                 + (ex2(hsum2(a2)) + ex2(hsum2(a3)));
        }
        // folding butterfly: 16 values -> per-batch totals in 16 shfls
#pragma unroll
        for (int j = 0; j < 8; j++) {
            const float send = (lane & 16) ? v[j] : v[j + 8];
            const float recv = __shfl_xor_sync(0xffffffffu, send, 16);
            const float mine = (lane & 16) ? v[j + 8] : v[j];
            v[j] = mine + recv;
        }
#pragma unroll
        for (int j = 0; j < 4; j++) {
            const float send = (lane & 8) ? v[j] : v[j + 4];
            const float recv = __shfl_xor_sync(0xffffffffu, send, 8);
            const float mine = (lane & 8) ? v[j + 4] : v[j];
            v[j] = mine + recv;
        }
#pragma unroll
        for (int j = 0; j < 2; j++) {
            const float send = (lane & 4) ? v[j] : v[j + 2];
            const float recv = __shfl_xor_sync(0xffffffffu, send, 4);
            const float mine = (lane & 4) ? v[j + 2] : v[j];
            v[j] = mine + recv;
        }
        {
            const float send = (lane & 2) ? v[0] : v[1];
            const float recv = __shfl_xor_sync(0xffffffffu, send, 2);
            const float mine = (lane & 2) ? v[1] : v[0];
            v[0] = mine + recv;
        }
        v[0] += __shfl_xor_sync(0xffffffffu, v[0], 1);
        if (!(lane & 1)) rS[warp][half * 16 + ((lane >> 1) & 15)] = v[0];
    }
    __syncthreads();
    if (tid < BATCH) {
        float S = 0.f;
#pragma unroll
        for (int wq = 0; wq < 8; wq++) S += rS[wq][tid];
        g_partS[(s * P1_TILES + bx) * BATCH + tid] = S;
    }
}

// ---------------------------------------------------------------------------
// Role: pass 2 (write log-probs for a 1024-vocab tile for timestep s).
// ---------------------------------------------------------------------------
__device__ __forceinline__ void p2_role(
    int s, int bx, int tid, char* sm,
    const float* __restrict__ W_ho, const float* __restrict__ b_ho,
    float* __restrict__ out) {
    ulonglong2 (*hs)[4] = (ulonglong2(*)[4])sm;               // 2048 B
    float* lz = (float*)(sm + 2048);                          // 128 B

    if (tid < 128)
        ((ulonglong2*)hs)[tid] = ((const ulonglong2*)(g_H + s * BATCH * HID))[tid];
    if (tid < 32) lz[tid] = g_logZ[s * BATCH + tid];
    __syncthreads();

    const int v0 = (bx * 256 + tid) * 4;
    if (v0 >= VOCAB) return;

    unsigned long long w[4][8];
    float bias[4];
#pragma unroll
    for (int r = 0; r < 4; r++) {
        const ulonglong2* wp = (const ulonglong2*)(W_ho + (v0 + r) * HID);
        const ulonglong2 wa = wp[0], wb = wp[1], wc = wp[2], wd = wp[3];
        w[r][0] = wa.x; w[r][1] = wa.y; w[r][2] = wb.x; w[r][3] = wb.y;
        w[r][4] = wc.x; w[r][5] = wc.y; w[r][6] = wd.x; w[r][7] = wd.y;
        bias[r] = b_ho[v0 + r];
    }

    float* orow = out + (size_t)s * BATCH * VOCAB + v0;
#pragma unroll 4
    for (int b = 0; b < BATCH; b++) {
        const ulonglong2 h01 = hs[b][0], h23 = hs[b][1];
        const ulonglong2 h45 = hs[b][2], h67 = hs[b][3];
        const float nl = -lz[b];
        unsigned long long a0 = packf2(bias[0], nl);
        unsigned long long a1 = packf2(bias[1], nl);
        unsigned long long a2 = packf2(bias[2], nl);
        unsigned long long a3 = packf2(bias[3], nl);
        ffma2(a0, w[0][0], h01.x); ffma2(a0, w[0][1], h01.y);
        ffma2(a0, w[0][2], h23.x); ffma2(a0, w[0][3], h23.y);
        ffma2(a0, w[0][4], h45.x); ffma2(a0, w[0][5], h45.y);
        ffma2(a0, w[0][6], h67.x); ffma2(a0, w[0][7], h67.y);
        ffma2(a1, w[1][0], h01.x); ffma2(a1, w[1][1], h01.y);
        ffma2(a1, w[1][2], h23.x); ffma2(a1, w[1][3], h23.y);
        ffma2(a1, w[1][4], h45.x); ffma2(a1, w[1][5], h45.y);
        ffma2(a1, w[1][6], h67.x); ffma2(a1, w[1][7], h67.y);
        ffma2(a2, w[2][0], h01.x); ffma2(a2, w[2][1], h01.y);
        ffma2(a2, w[2][2], h23.x); ffma2(a2, w[2][3], h23.y);
        ffma2(a2, w[2][4], h45.x); ffma2(a2, w[2][5], h45.y);
        ffma2(a2, w[2][6], h67.x); ffma2(a2, w[2][7], h67.y);
        ffma2(a3, w[3][0], h01.x); ffma2(a3, w[3][1], h01.y);
        ffma2(a3, w[3][2], h23.x); ffma2(a3, w[3][3], h23.y);
        ffma2(a3, w[3][4], h45.x); ffma2(a3, w[3][5], h45.y);
        ffma2(a3, w[3][6], h67.x); ffma2(a3, w[3][7], h67.y);
        float4 res;
        res.x = hsum2(a0);
        res.y = hsum2(a1);
        res.z = hsum2(a2);
        res.w = hsum2(a3);
        __stcs((float4*)(orow + (size_t)b * VOCAB), res);
    }
}

// ---------------------------------------------------------------------------
// Mixed kernel: grid (64, CH). x<32 -> p1 for s=off1+y; x>=32 -> p2 for
// s=off2+y. off<0 disables that role (blocks exit immediately).
// Dependencies are carried by stream order of launches -- no flags/spinning.
// ---------------------------------------------------------------------------
__global__ __launch_bounds__(256, 2)
void mixed_kernel(const float* __restrict__ W_ho,
                  const float* __restrict__ b_ho,
                  float* __restrict__ out,
                  int off1, int off2) {
    __shared__ __align__(16) char sm[3072];
    const int x = blockIdx.x;
    if (x < 32) {
        if (off1 >= 0) p1_role(off1 + blockIdx.y, x, threadIdx.x, sm, W_ho, b_ho);
    } else {
        if (off2 >= 0) p2_role(off2 + blockIdx.y, x - 32, threadIdx.x, sm, W_ho, b_ho, out);
    }
}

// ---------------------------------------------------------------------------
// Combine for one chunk: logZ for s in [s0, s0+CH). 4 blocks x 256 threads.
// ---------------------------------------------------------------------------
__global__ void combine_kernel(int s0) {
    const int id = blockIdx.x * blockDim.x + threadIdx.x;  // 0..1023
    const int s = s0 + (id >> 5);
    const int b = id & 31;
    float S = 0.f;
#pragma unroll
    for (int t = 0; t < P1_TILES; t++) S += g_partS[(s * P1_TILES + t) * BATCH + b];
    g_logZ[s * BATCH + b] = __logf(S);
}

// ---------------------------------------------------------------------------
// Launcher. Input order: input_batch, h0, embedding, W_ih, b_ih, W_ho, b_ho.
// Pipeline: recur; p1(c0); comb(c0); [p1(c1)+p2(c0)]; comb(c1); ...; p2(c3).
// ---------------------------------------------------------------------------
extern "C" void kernel_launch(void* const* d_in, const int* in_sizes, int n_in,
                              void* d_out, int out_size) {
    const int*   idx  = (const int*)  d_in[0];
    const float* h0   = (const float*)d_in[1];
    const float* emb  = (const float*)d_in[2];
    const float* W_ih = (const float*)d_in[3];
    const float* b_ih = (const float*)d_in[4];
    const float* W_ho = (const float*)d_in[5];
    const float* b_ho = (const float*)d_in[6];
    float* out = (float*)d_out;

    recur_kernel<<<BATCH, 32>>>(idx, h0, emb, W_ih, b_ih);
    for (int c = 0; c <= NCH; c++) {
        const int off1 = (c < NCH) ? c * CH : -1;
        const int off2 = (c > 0) ? (c - 1) * CH : -1;
        mixed_kernel<<<dim3(64, CH), 256>>>(W_ho, b_ho, out, off1, off2);
        if (c < NCH) combine_kernel<<<4, 256>>>(c * CH);
    }
}

// round 11
// speedup vs baseline: 1.6149x; 1.6149x over previous
#include <cuda_runtime.h>
#include <cuda_fp16.h>
#include <cstdint>
#include <math.h>
#include <math_constants.h>

#define SEQ   128
#define BATCH 32
#define EMB   32
#define HID   16
#define VOCAB 32000
#define VPAD  32768        // padded vocab (pad rows contribute 0 to sum-exp)
#define CIN   48           // EMB + HID

#define VSPLIT   16        // x-blocks in p1 (each covers 2048 vocab)
#define P2_TILES 32
#define LOG2E 1.4426950408889634f

// Scratch (no allocations allowed)
__device__ float  g_H[SEQ * BATCH * HID];          // fp32 h for p2
__device__ __half g_Hhf[SEQ * BATCH * HID];        // fp16 h * log2e for p1 MMA
__device__ __half g_Whf[VPAD * HID];               // fp16 W_ho (pad rows = 0)
__device__ float  g_b2[VPAD];                      // b_ho * log2e (pad = -2000)
__device__ float  g_partS[SEQ * VSPLIT * BATCH];
__device__ float  g_logZ[SEQ * BATCH];

// ---- packed f32x2 helpers ---------------------------------------------------
__device__ __forceinline__ void ffma2(unsigned long long& d,
                                      unsigned long long a,
                                      unsigned long long b) {
    asm("fma.rn.f32x2 %0, %1, %2, %0;" : "+l"(d) : "l"(a), "l"(b));
}
__device__ __forceinline__ float hsum2(unsigned long long v) {
    float lo, hi;
    asm("mov.b64 {%0, %1}, %2;" : "=f"(lo), "=f"(hi) : "l"(v));
    return lo + hi;
}
__device__ __forceinline__ unsigned long long packf2(float lo, float hi) {
    unsigned long long d;
    asm("mov.b64 %0, {%1, %2};" : "=l"(d) : "f"(lo), "f"(hi));
    return d;
}
__device__ __forceinline__ float ex2(float x) {
    float r;
    asm("ex2.approx.f32 %0, %1;" : "=f"(r) : "f"(x));
    return r;
}

// mma.sync m16n8k16: D(f32) = A(f16) * B(f16) + C(f32)
__device__ __forceinline__ void mma16816(float& d0, float& d1, float& d2, float& d3,
                                         unsigned a0, unsigned a1, unsigned a2, unsigned a3,
                                         unsigned b0, unsigned b1) {
    const float z = 0.f;
    asm volatile(
        "mma.sync.aligned.m16n8k16.row.col.f32.f16.f16.f32 "
        "{%0,%1,%2,%3}, {%4,%5,%6,%7}, {%8,%9}, {%10,%11,%12,%13};"
        : "=f"(d0), "=f"(d1), "=f"(d2), "=f"(d3)
        : "r"(a0), "r"(a1), "r"(a2), "r"(a3), "r"(b0), "r"(b1),
          "f"(z), "f"(z), "f"(z), "f"(z));
}

// ---------------------------------------------------------------------------
// Prep: fp16 W (pad rows 0) and log2-scaled bias (pad -2000 -> ex2 = 0).
// ---------------------------------------------------------------------------
__global__ __launch_bounds__(256)
void prep_kernel(const float* __restrict__ W_ho, const float* __restrict__ b_ho) {
    const int row = blockIdx.x * 256 + threadIdx.x;
    if (row >= VPAD) return;
    __half* d = g_Whf + row * HID;
    if (row < VOCAB) {
#pragma unroll
        for (int k = 0; k < HID; k++) d[k] = __float2half(W_ho[row * HID + k]);
        g_b2[row] = b_ho[row] * LOG2E;
    } else {
#pragma unroll
        for (int k = 0; k < HID; k++) d[k] = __float2half(0.f);
        g_b2[row] = -2000.f;
    }
}

// ---------------------------------------------------------------------------
// Kernel A: recurrence. 32 single-warp blocks; writes fp32 h and fp16 h*log2e.
// ---------------------------------------------------------------------------
__global__ __launch_bounds__(32, 1)
void recur_kernel(const int*   __restrict__ idx,
                  const float* __restrict__ h0,
                  const float* __restrict__ emb,
                  const float* __restrict__ W_ih,
                  const float* __restrict__ b_ih) {
    const int b    = blockIdx.x;
    const int lane = threadIdx.x;
    const int i    = lane & 15;
    const int half = lane >> 4;

    __shared__ int   idxs[SEQ];
    __shared__ float comb[CIN];

    for (int t = lane; t < SEQ; t += 32) idxs[t] = idx[t * BATCH + b];

    float wih[24];
    const int base = half * 24;
#pragma unroll
    for (int j = 0; j < 24; j++) wih[j] = W_ih[i * CIN + base + j];
    const float bias = b_ih[i];

    __syncwarp();

    float x = emb[idxs[0] * EMB + lane];
    float h = (lane < 16) ? h0[b * HID + lane] : 0.f;

    for (int t = 0; t < SEQ; t++) {
        comb[lane] = x;
        if (lane < 16) comb[EMB + lane] = h;
        __syncwarp();

        if (t + 1 < SEQ) x = emb[idxs[t + 1] * EMB + lane];

        float a0 = 0.f, a1 = 0.f, a2 = 0.f;
#pragma unroll
        for (int j = 0; j < 24; j += 3) {
            a0 += wih[j]     * comb[base + j];
            a1 += wih[j + 1] * comb[base + j + 1];
            a2 += wih[j + 2] * comb[base + j + 2];
        }
        float part = (a0 + a1) + a2;
        part += __shfl_xor_sync(0xffffffffu, part, 16);

        const float z = part + bias;
        const float e = ex2(2.f * LOG2E * z);
        const float hn = __fdividef(e - 1.f, e + 1.f);

        __syncwarp();
        if (lane < 16) {
            h = hn;
            g_H[(t * BATCH + b) * HID + i] = hn;
            g_Hhf[(t * BATCH + b) * HID + i] = __float2half(hn * LOG2E);
        }
    }
}

// ---------------------------------------------------------------------------
// Kernel B (p1 via HMMA): sum-exp of logits on the tensor pipe.
// Block = (vstrip, s), 8 warps. Warp covers 256 vocab in 32 tiles of 8.
// Per tile: 2 mma.m16n8k16 (batch halves 0-15 / 16-31), epilogue ex2+acc.
// A = h*log2e (fp16), B = W (fp16), bias (log2) added in epilogue.
// ---------------------------------------------------------------------------
__global__ __launch_bounds__(256, 4)
void p1_mma() {
    const int s    = blockIdx.y;
    const int bx   = blockIdx.x;
    const int tid  = threadIdx.x;
    const int warp = tid >> 5;
    const int lane = tid & 31;

    __shared__ float rS[8][BATCH];

    const int g  = lane >> 2;        // group id 0..7
    const int c4 = (lane & 3) * 2;   // k-pair / col base

    // A fragments (batches 0-15 and 16-31), k = 16
    const __half* Ah = g_Hhf + s * BATCH * HID;
    const unsigned a0 = *(const unsigned*)(Ah + (g)      * HID + c4);
    const unsigned a1 = *(const unsigned*)(Ah + (g + 8)  * HID + c4);
    const unsigned a2 = *(const unsigned*)(Ah + (g)      * HID + c4 + 8);
    const unsigned a3 = *(const unsigned*)(Ah + (g + 8)  * HID + c4 + 8);
    const unsigned a4 = *(const unsigned*)(Ah + (g + 16) * HID + c4);
    const unsigned a5 = *(const unsigned*)(Ah + (g + 24) * HID + c4);
    const unsigned a6 = *(const unsigned*)(Ah + (g + 16) * HID + c4 + 8);
    const unsigned a7 = *(const unsigned*)(Ah + (g + 24) * HID + c4 + 8);

    float s0 = 0.f, s1 = 0.f, s2 = 0.f, s3 = 0.f;

    const int vwarp = bx * 2048 + warp * 256;
#pragma unroll 4
    for (int tile = 0; tile < 32; tile++) {
        const int v0 = vwarp + tile * 8;
        // B fragment: n = g, k-pairs at c4 and c4+8
        const __half* Bp = g_Whf + (v0 + g) * HID;
        const unsigned b0 = *(const unsigned*)(Bp + c4);
        const unsigned b1 = *(const unsigned*)(Bp + c4 + 8);
        const float2 bb = *(const float2*)(g_b2 + v0 + c4);

        float d0, d1, d2, d3, e0, e1, e2, e3;
        mma16816(d0, d1, d2, d3, a0, a1, a2, a3, b0, b1);
        mma16816(e0, e1, e2, e3, a4, a5, a6, a7, b0, b1);

        s0 += ex2(d0 + bb.x) + ex2(d1 + bb.y);   // batch g
        s1 += ex2(d2 + bb.x) + ex2(d3 + bb.y);   // batch g+8
        s2 += ex2(e0 + bb.x) + ex2(e1 + bb.y);   // batch g+16
        s3 += ex2(e2 + bb.x) + ex2(e3 + bb.y);   // batch g+24
    }

    // reduce over the 4 lanes sharing each batch row (lane&3 varies)
    s0 += __shfl_xor_sync(0xffffffffu, s0, 1); s0 += __shfl_xor_sync(0xffffffffu, s0, 2);
    s1 += __shfl_xor_sync(0xffffffffu, s1, 1); s1 += __shfl_xor_sync(0xffffffffu, s1, 2);
    s2 += __shfl_xor_sync(0xffffffffu, s2, 1); s2 += __shfl_xor_sync(0xffffffffu, s2, 2);
    s3 += __shfl_xor_sync(0xffffffffu, s3, 1); s3 += __shfl_xor_sync(0xffffffffu, s3, 2);
    if ((lane & 3) == 0) {
        rS[warp][g]      = s0;
        rS[warp][g + 8]  = s1;
        rS[warp][g + 16] = s2;
        rS[warp][g + 24] = s3;
    }
    __syncthreads();
    if (tid < BATCH) {
        float S = 0.f;
#pragma unroll
        for (int w = 0; w < 8; w++) S += rS[w][tid];
        g_partS[(s * VSPLIT + bx) * BATCH + tid] = S;
    }
}

// ---------------------------------------------------------------------------
// Kernel C: combine vstrip partials -> logZ. 4096 threads.
// ---------------------------------------------------------------------------
__global__ void combine_kernel() {
    const int id = blockIdx.x * blockDim.x + threadIdx.x;  // 0..4095
    const int s = id >> 5;
    const int b = id & 31;
    float S = 0.f;
#pragma unroll
    for (int t = 0; t < VSPLIT; t++) S += g_partS[(s * VSPLIT + t) * BATCH + b];
    // logZ in nats: S is sum of 2^(log2-logit) = sum e^logit
    g_logZ[id] = __logf(S);
}

// ---------------------------------------------------------------------------
// Kernel D (pass 2): exact fp32 recompute, write logit - logZ. Unchanged.
// ---------------------------------------------------------------------------
__global__ __launch_bounds__(256, 2)
void logits_pass2(const float* __restrict__ W_ho,
                  const float* __restrict__ b_ho,
                  float* __restrict__ out) {
    const int s   = blockIdx.y;
    const int tid = threadIdx.x;

    __shared__ ulonglong2 hs[BATCH][4];
    __shared__ float      lz[BATCH];
    if (tid < 128)
        ((ulonglong2*)hs)[tid] = ((const ulonglong2*)(g_H + s * BATCH * HID))[tid];
    if (tid < 32) lz[tid] = g_logZ[s * BATCH + tid];
    __syncthreads();

    const int v0 = (blockIdx.x * 256 + tid) * 4;
    if (v0 >= VOCAB) return;

    unsigned long long w[4][8];
    float bias[4];
#pragma unroll
    for (int r = 0; r < 4; r++) {
        const ulonglong2* wp = (const ulonglong2*)(W_ho + (v0 + r) * HID);
        const ulonglong2 wa = wp[0], wb = wp[1], wc = wp[2], wd = wp[3];
        w[r][0] = wa.x; w[r][1] = wa.y; w[r][2] = wb.x; w[r][3] = wb.y;
        w[r][4] = wc.x; w[r][5] = wc.y; w[r][6] = wd.x; w[r][7] = wd.y;
        bias[r] = b_ho[v0 + r];
    }

    float* orow = out + (size_t)s * BATCH * VOCAB + v0;
#pragma unroll 4
    for (int b = 0; b < BATCH; b++) {
        const ulonglong2 h01 = hs[b][0], h23 = hs[b][1];
        const ulonglong2 h45 = hs[b][2], h67 = hs[b][3];
        const float nl = -lz[b];
        unsigned long long a0 = packf2(bias[0], nl);
        unsigned long long a1 = packf2(bias[1], nl);
        unsigned long long a2 = packf2(bias[2], nl);
        unsigned long long a3 = packf2(bias[3], nl);
        ffma2(a0, w[0][0], h01.x); ffma2(a0, w[0][1], h01.y);
        ffma2(a0, w[0][2], h23.x); ffma2(a0, w[0][3], h23.y);
        ffma2(a0, w[0][4], h45.x); ffma2(a0, w[0][5], h45.y);
        ffma2(a0, w[0][6], h67.x); ffma2(a0, w[0][7], h67.y);
        ffma2(a1, w[1][0], h01.x); ffma2(a1, w[1][1], h01.y);
        ffma2(a1, w[1][2], h23.x); ffma2(a1, w[1][3], h23.y);
        ffma2(a1, w[1][4], h45.x); ffma2(a1, w[1][5], h45.y);
        ffma2(a1, w[1][6], h67.x); ffma2(a1, w[1][7], h67.y);
        ffma2(a2, w[2][0], h01.x); ffma2(a2, w[2][1], h01.y);
        ffma2(a2, w[2][2], h23.x); ffma2(a2, w[2][3], h23.y);
        ffma2(a2, w[2][4], h45.x); ffma2(a2, w[2][5], h45.y);
        ffma2(a2, w[2][6], h67.x); ffma2(a2, w[2][7], h67.y);
        ffma2(a3, w[3][0], h01.x); ffma2(a3, w[3][1], h01.y);
        ffma2(a3, w[3][2], h23.x); ffma2(a3, w[3][3], h23.y);
        ffma2(a3, w[3][4], h45.x); ffma2(a3, w[3][5], h45.y);
        ffma2(a3, w[3][6], h67.x); ffma2(a3, w[3][7], h67.y);
        float4 res;
        res.x = hsum2(a0);
        res.y = hsum2(a1);
        res.z = hsum2(a2);
        res.w = hsum2(a3);
        __stcs((float4*)(orow + (size_t)b * VOCAB), res);
    }
}

// ---------------------------------------------------------------------------
// Launcher. Input order: input_batch, h0, embedding, W_ih, b_ih, W_ho, b_ho.
// ---------------------------------------------------------------------------
extern "C" void kernel_launch(void* const* d_in, const int* in_sizes, int n_in,
                              void* d_out, int out_size) {
    const int*   idx  = (const int*)  d_in[0];
    const float* h0   = (const float*)d_in[1];
    const float* emb  = (const float*)d_in[2];
    const float* W_ih = (const float*)d_in[3];
    const float* b_ih = (const float*)d_in[4];
    const float* W_ho = (const float*)d_in[5];
    const float* b_ho = (const float*)d_in[6];
    float* out = (float*)d_out;

    prep_kernel<<<VPAD / 256, 256>>>(W_ho, b_ho);
    recur_kernel<<<BATCH, 32>>>(idx, h0, emb, W_ih, b_ih);
    p1_mma<<<dim3(VSPLIT, SEQ), 256>>>();
    combine_kernel<<<16, 256>>>();
    logits_pass2<<<dim3(P2_TILES, SEQ), 256>>>(W_ho, b_ho, out);
}